// round 4
// baseline (speedup 1.0000x reference)
#include <cuda_runtime.h>
#include <cuda_bf16.h>
#include <cstdint>

#define N_NODES 20000
#define BATCH 512
#define EMBED_DIM 32
#define NUM_SAMPLES 5001
#define TD_MAX 5000.0f

#define N4 (N_NODES / 4)        // 5000 float4 per row
#define NTILES 20               // x-tiles of 250 float4 (1000 nodes)
#define TILE4 250               // float4 per tile
#define BGROUPS 16              // batch groups
#define BG 32                   // b per group
#define LAMBDA_BLOCKS (NTILES * BGROUPS)   // 320
#define TOTAL_BLOCKS (LAMBDA_BLOCKS + BATCH)  // 320 + 512
#define CHUNK 20                // 256*20 >= 5001

#define L2E 1.4426950408889634f
#define LN2 0.6931471805599453f

// ps * softplus(x), psln2 = ps*ln2 prefolded
__device__ __forceinline__ float sp_scaled(float x, float ps, float psln2) {
    float e  = exp2f(-L2E * fabsf(x));
    float lg = __log2f(1.0f + e);
    return fmaf(lg, psln2, ps * fmaxf(x, 0.0f));
}

__device__ __forceinline__ float dot32(const float* __restrict__ a,
                                       const float* __restrict__ w) {
    const float4* a4 = (const float4*)a;
    const float4* w4 = (const float4*)w;
    float s = 0.f;
    #pragma unroll
    for (int q = 0; q < 8; q++) {
        float4 r = __ldg(a4 + q);
        float4 c = __ldg(w4 + q);
        s = fmaf(r.x, c.x, fmaf(r.y, c.y, fmaf(r.z, c.z, fmaf(r.w, c.w, s))));
    }
    return s;
}

// ---------------------------------------------------------------------------
// Single fused kernel.
//   blockIdx.x < LAMBDA_BLOCKS : lambda tile (xt = id%20, bg = id/20, 32 b's)
//   else                       : return_time scan for b = blockIdx.x - 320
// ---------------------------------------------------------------------------
__global__ void __launch_bounds__(256) decoder_kernel(
    float* __restrict__ out,
    const float* __restrict__ emb,
    const int*   __restrict__ assoc,
    const int*   __restrict__ src,
    const int*   __restrict__ pdst,
    const float* __restrict__ last_update,
    const float* __restrict__ cur_time,
    const int*   __restrict__ et,
    const float* __restrict__ W0,
    const float* __restrict__ b0,
    const float* __restrict__ W1,
    const float* __restrict__ b1,
    const float* __restrict__ psi,
    const float* __restrict__ alpha,
    const float* __restrict__ w_t)
{
    int t = threadIdx.x;

    // Block-uniform per-event-type constants
    float ps0 = __ldg(psi);
    float ps1 = __ldg(psi + 1);
    float inv0 = 1.0f / (ps0 + 1e-7f);
    float inv1 = 1.0f / (ps1 + 1e-7f);

    if (blockIdx.x < LAMBDA_BLOCKS) {
        // ================= lambda tile block =================
        int xt = blockIdx.x % NTILES;
        int bg = blockIdx.x / NTILES;
        int x  = xt * TILE4 + t;            // float4 index in [0, 5000)

        __shared__ float sm_cs[BG];         // (s + a*exp) * inv_e
        __shared__ float sm_cd[BG];
        __shared__ int   sm_e[BG];

        // ---- per-thread projections for 4 nodes, pre-scaled by inv_e ----
        float4 U0, U1, V0, V1;              // U = node_u*inv, V = node_v*inv
        if (t < TILE4) {
            float* pu0 = &U0.x; float* pu1 = &U1.x;
            float* pv0 = &V0.x; float* pv1 = &V1.x;
            #pragma unroll
            for (int j = 0; j < 4; j++) {
                const float* row = emb + (size_t)(4 * x + j) * EMBED_DIM;
                pu0[j] = dot32(row, W0)      * inv0;
                pv0[j] = dot32(row, W0 + 32) * inv0;
                pu1[j] = dot32(row, W1)      * inv1;
                pv1[j] = dot32(row, W1 + 32) * inv1;
            }
        }

        // ---- batch scalars for this block's 32 b's (threads 0..31) ----
        if (t < BG) {
            int b = bg * BG + t;
            int e = (__ldg(et + b) > 0) ? 1 : 0;
            int is = __ldg(assoc + __ldg(src + b));
            int id = __ldg(assoc + __ldg(pdst + b));
            const float* Wu = e ? W1 : W0;
            float bb = e ? __ldg(b1) : __ldg(b0);
            float s = dot32(emb + (size_t)is * EMBED_DIM, Wu)      + bb;
            float d = dot32(emb + (size_t)id * EMBED_DIM, Wu + 32) + bb;
            float al = __ldg(alpha + e), w = __ldg(w_t + e);
            float inv = e ? inv1 : inv0;
            float ct  = __ldg(cur_time + b);
            float tds = (ct - __ldg(last_update + is)) * (1.0f / TD_MAX);
            float tdd = (ct - __ldg(last_update + id)) * (1.0f / TD_MAX);
            sm_cs[t] = (s + al * __expf(-w * tds)) * inv;
            sm_cd[t] = (d + al * __expf(-w * tdd)) * inv;
            sm_e[t]  = e;
        }
        __syncthreads();

        if (t >= TILE4) return;

        float psl0 = ps0 * LN2, psl1 = ps1 * LN2;
        float* outs = out + (size_t)(bg * BG) * N_NODES + 4 * x;
        float* outd = outs + (size_t)BATCH * N_NODES;

        #pragma unroll 2
        for (int bb = 0; bb < BG; bb++) {
            int   e     = sm_e[bb];
            float cs    = sm_cs[bb];
            float cd    = sm_cd[bb];
            float ps    = e ? ps1  : ps0;
            float psln2 = e ? psl1 : psl0;
            float4 U    = e ? U1 : U0;
            float4 V    = e ? V1 : V0;

            float4 ls, ld;
            ls.x = sp_scaled(V.x + cs, ps, psln2);
            ls.y = sp_scaled(V.y + cs, ps, psln2);
            ls.z = sp_scaled(V.z + cs, ps, psln2);
            ls.w = sp_scaled(V.w + cs, ps, psln2);
            ld.x = sp_scaled(U.x + cd, ps, psln2);
            ld.y = sp_scaled(U.y + cd, ps, psln2);
            ld.z = sp_scaled(U.z + cd, ps, psln2);
            ld.w = sp_scaled(U.w + cd, ps, psln2);

            *(float4*)(outs) = ls;
            *(float4*)(outd) = ld;
            outs += N_NODES;
            outd += N_NODES;
        }
        return;
    }

    // ================= return_time block (one b) =================
    int b = blockIdx.x - LAMBDA_BLOCKS;

    __shared__ float sm_bp[4];   // gbi, ali, wtn, ps

    if (t < 32) {
        int e = (__ldg(et + b) > 0) ? 1 : 0;
        int is = __ldg(assoc + __ldg(src + b));
        int id = __ldg(assoc + __ldg(pdst + b));
        const float* Wu = e ? W1 : W0;
        // warp-parallel dots: lane k handles component k
        float sp = __ldg(emb + (size_t)is * EMBED_DIM + t) * __ldg(Wu + t);
        float dp = __ldg(emb + (size_t)id * EMBED_DIM + t) * __ldg(Wu + 32 + t);
        #pragma unroll
        for (int o = 16; o > 0; o >>= 1) {
            sp += __shfl_down_sync(0xffffffffu, sp, o);
            dp += __shfl_down_sync(0xffffffffu, dp, o);
        }
        if (t == 0) {
            float bb = e ? __ldg(b1) : __ldg(b0);
            float gb = sp + dp + bb;
            float inv = e ? inv1 : inv0;
            sm_bp[0] = gb * inv;
            sm_bp[1] = __ldg(alpha + e) * inv;
            sm_bp[2] = __ldg(w_t + e) * (L2E / TD_MAX);
            sm_bp[3] = e ? ps1 : ps0;
        }
    }
    __syncthreads();

    float gbi = sm_bp[0], ali = sm_bp[1], wtn = sm_bp[2], ps = sm_bp[3];
    float psln2 = ps * LN2;

    int i0 = t * CHUNK;
    float loc[CHUNK];
    float s = 0.f;
    #pragma unroll
    for (int k = 0; k < CHUNK; k++) {
        int i = i0 + k;
        float inten = 0.f;
        if (i < NUM_SAMPLES) {
            float exc = exp2f(-wtn * (float)i);
            inten = sp_scaled(fmaf(exc, ali, gbi), ps, psln2);
        }
        loc[k] = inten;
        s += inten;
    }

    // Block exclusive scan of per-thread sums
    unsigned m = 0xffffffffu;
    float v = s;
    #pragma unroll
    for (int o = 1; o < 32; o <<= 1) {
        float n = __shfl_up_sync(m, v, o);
        if ((t & 31) >= o) v += n;
    }
    __shared__ float wsum[8];
    if ((t & 31) == 31) wsum[t >> 5] = v;
    __syncthreads();
    if (t < 8) {
        float w = wsum[t];
        #pragma unroll
        for (int o = 1; o < 8; o <<= 1) {
            float n = __shfl_up_sync(0xffu, w, o);
            if (t >= o) w += n;
        }
        wsum[t] = w;
    }
    __syncthreads();
    float excl = (v - s) + ((t >= 32) ? wsum[(t >> 5) - 1] : 0.f);

    float run = excl;
    float acc = 0.f;
    #pragma unroll
    for (int k = 0; k < CHUNK; k++) {
        int i = i0 + k;
        if (i < NUM_SAMPLES) {
            run += loc[k];                         // integral_i (TIMESTEP=1)
            float dens = loc[k] * exp2f(-L2E * run);
            float wgt = (i == NUM_SAMPLES - 1) ? 0.5f : 1.0f;  // i==0 term is 0
            acc = fmaf(wgt * (float)i, dens, acc);
        }
    }

    #pragma unroll
    for (int o = 16; o > 0; o >>= 1) acc += __shfl_down_sync(m, acc, o);
    __shared__ float rsum[8];
    if ((t & 31) == 0) rsum[t >> 5] = acc;
    __syncthreads();
    if (t == 0) {
        float tot = 0.f;
        #pragma unroll
        for (int wgrp = 0; wgrp < 8; wgrp++) tot += rsum[wgrp];
        out[(size_t)2 * BATCH * N_NODES + b] = tot;
    }
}

// ---------------------------------------------------------------------------
extern "C" void kernel_launch(void* const* d_in, const int* in_sizes, int n_in,
                              void* d_out, int out_size)
{
    const float* emb   = (const float*)d_in[0];
    const int*   assoc = (const int*)  d_in[1];
    const int*   src   = (const int*)  d_in[2];
    const int*   pdst  = (const int*)  d_in[3];
    const float* lu    = (const float*)d_in[5];
    const float* ct    = (const float*)d_in[6];
    const int*   et    = (const int*)  d_in[7];
    const float* W0    = (const float*)d_in[8];
    const float* b0    = (const float*)d_in[9];
    const float* W1    = (const float*)d_in[10];
    const float* b1    = (const float*)d_in[11];
    const float* psi   = (const float*)d_in[12];
    const float* alpha = (const float*)d_in[13];
    const float* w_t   = (const float*)d_in[14];

    decoder_kernel<<<TOTAL_BLOCKS, 256>>>((float*)d_out, emb, assoc, src, pdst,
                                          lu, ct, et, W0, b0, W1, b1,
                                          psi, alpha, w_t);
}

// round 7
// speedup vs baseline: 1.0357x; 1.0357x over previous
#include <cuda_runtime.h>
#include <cuda_bf16.h>
#include <cstdint>

#define N_NODES 20000
#define BATCH 512
#define EMBED_DIM 32
#define NUM_SAMPLES 5001
#define TD_MAX 5000.0f

#define TILE 256                  // nodes per lambda block (1 per thread)
#define NTILES ((N_NODES + TILE - 1) / TILE)   // 79
#define BG 64                     // batch rows per lambda block
#define BGROUPS (BATCH / BG)      // 8
#define LAMBDA_BLOCKS (NTILES * BGROUPS)       // 632
#define TOTAL_BLOCKS (LAMBDA_BLOCKS + BATCH)   // 632 + 512
#define CHUNK 20                  // 256*20 >= 5001

#define L2E 1.4426950408889634f
#define LN2 0.6931471805599453f

// ps * softplus(x), psln2 = ps*ln2 prefolded
__device__ __forceinline__ float sp_scaled(float x, float ps, float psln2) {
    float e  = exp2f(-L2E * fabsf(x));
    float lg = __log2f(1.0f + e);
    return fmaf(lg, psln2, ps * fmaxf(x, 0.0f));
}

__device__ __forceinline__ float dot32(const float* __restrict__ a,
                                       const float* __restrict__ w) {
    const float4* a4 = (const float4*)a;
    const float4* w4 = (const float4*)w;
    float s = 0.f;
    #pragma unroll
    for (int q = 0; q < 8; q++) {
        float4 r = __ldg(a4 + q);
        float4 c = __ldg(w4 + q);
        s = fmaf(r.x, c.x, fmaf(r.y, c.y, fmaf(r.z, c.z, fmaf(r.w, c.w, s))));
    }
    return s;
}

// ---------------------------------------------------------------------------
// Single fused kernel.
//  blockIdx.x < LAMBDA_BLOCKS : lambda tile (tile = id%79, bgroup = id/79)
//  else                       : return_time scan for b = blockIdx.x - 632
// ---------------------------------------------------------------------------
__global__ void __launch_bounds__(256, 6) decoder_kernel(
    float* __restrict__ out,
    const float* __restrict__ emb,
    const int*   __restrict__ assoc,
    const int*   __restrict__ src,
    const int*   __restrict__ pdst,
    const float* __restrict__ last_update,
    const float* __restrict__ cur_time,
    const int*   __restrict__ et,
    const float* __restrict__ W0,
    const float* __restrict__ b0,
    const float* __restrict__ W1,
    const float* __restrict__ b1,
    const float* __restrict__ psi,
    const float* __restrict__ alpha,
    const float* __restrict__ w_t)
{
    int t = threadIdx.x;

    float ps0 = __ldg(psi);
    float ps1 = __ldg(psi + 1);
    float inv0 = 1.0f / (ps0 + 1e-7f);
    float inv1 = 1.0f / (ps1 + 1e-7f);

    if (blockIdx.x < LAMBDA_BLOCKS) {
        // ================= lambda block =================
        int tile = blockIdx.x % NTILES;
        int bg   = blockIdx.x / NTILES;
        int node = tile * TILE + t;
        bool live = (node < N_NODES);

        __shared__ float sm_cs[BG];     // (s + a*exp(..)) * inv_e
        __shared__ float sm_cd[BG];
        __shared__ int   sm_e[BG];

        // per-thread projections for ONE node, pre-scaled by inv_e (4 regs)
        float u0 = 0.f, v0 = 0.f, u1 = 0.f, v1 = 0.f;
        if (live) {
            const float* row = emb + (size_t)node * EMBED_DIM;
            u0 = dot32(row, W0)      * inv0;
            v0 = dot32(row, W0 + 32) * inv0;
            u1 = dot32(row, W1)      * inv1;
            v1 = dot32(row, W1 + 32) * inv1;
        }

        // batch scalars for this block's 64 b's (threads 0..63)
        if (t < BG) {
            int b = bg * BG + t;
            int e = (__ldg(et + b) > 0) ? 1 : 0;
            int is = __ldg(assoc + __ldg(src + b));
            int id = __ldg(assoc + __ldg(pdst + b));
            const float* Wu = e ? W1 : W0;
            float bb = e ? __ldg(b1) : __ldg(b0);
            float s = dot32(emb + (size_t)is * EMBED_DIM, Wu)      + bb;
            float d = dot32(emb + (size_t)id * EMBED_DIM, Wu + 32) + bb;
            float al = __ldg(alpha + e), w = __ldg(w_t + e);
            float inv = e ? inv1 : inv0;
            float ct  = __ldg(cur_time + b);
            float tds = (ct - __ldg(last_update + is)) * (1.0f / TD_MAX);
            float tdd = (ct - __ldg(last_update + id)) * (1.0f / TD_MAX);
            sm_cs[t] = (s + al * __expf(-w * tds)) * inv;
            sm_cd[t] = (d + al * __expf(-w * tdd)) * inv;
            sm_e[t]  = e;
        }
        __syncthreads();

        if (!live) return;

        float psl0 = ps0 * LN2, psl1 = ps1 * LN2;
        float* outs = out + (size_t)(bg * BG) * N_NODES + node;
        float* outd = outs + (size_t)BATCH * N_NODES;

        #pragma unroll 8
        for (int bb = 0; bb < BG; bb++) {
            int   e     = sm_e[bb];
            float ps    = e ? ps1  : ps0;
            float psln2 = e ? psl1 : psl0;
            float un    = e ? u1 : u0;
            float vn    = e ? v1 : v0;

            float ls = sp_scaled(vn + sm_cs[bb], ps, psln2);   // lambda_src
            float ld = sp_scaled(un + sm_cd[bb], ps, psln2);   // lambda_dst
            outs[0] = ls;
            outd[0] = ld;
            outs += N_NODES;
            outd += N_NODES;
        }
        return;
    }

    // ================= return_time block (one b) =================
    int b = blockIdx.x - LAMBDA_BLOCKS;

    __shared__ float sm_bp[4];   // gbi, ali, wtn, ps

    if (t < 32) {
        int e = (__ldg(et + b) > 0) ? 1 : 0;
        int is = __ldg(assoc + __ldg(src + b));
        int id = __ldg(assoc + __ldg(pdst + b));
        const float* Wu = e ? W1 : W0;
        float sp = __ldg(emb + (size_t)is * EMBED_DIM + t) * __ldg(Wu + t);
        float dp = __ldg(emb + (size_t)id * EMBED_DIM + t) * __ldg(Wu + 32 + t);
        #pragma unroll
        for (int o = 16; o > 0; o >>= 1) {
            sp += __shfl_down_sync(0xffffffffu, sp, o);
            dp += __shfl_down_sync(0xffffffffu, dp, o);
        }
        if (t == 0) {
            float bb = e ? __ldg(b1) : __ldg(b0);
            float inv = e ? inv1 : inv0;
            sm_bp[0] = (sp + dp + bb) * inv;
            sm_bp[1] = __ldg(alpha + e) * inv;
            sm_bp[2] = __ldg(w_t + e) * (L2E / TD_MAX);
            sm_bp[3] = e ? ps1 : ps0;
        }
    }
    __syncthreads();

    float gbi = sm_bp[0], ali = sm_bp[1], wtn = sm_bp[2], ps = sm_bp[3];
    float psln2 = ps * LN2;

    int i0 = t * CHUNK;
    float loc[CHUNK];
    float s = 0.f;
    #pragma unroll
    for (int k = 0; k < CHUNK; k++) {
        int i = i0 + k;
        float inten = 0.f;
        if (i < NUM_SAMPLES) {
            float exc = exp2f(-wtn * (float)i);
            inten = sp_scaled(fmaf(exc, ali, gbi), ps, psln2);
        }
        loc[k] = inten;
        s += inten;
    }

    // Block exclusive scan of per-thread sums
    unsigned m = 0xffffffffu;
    float v = s;
    #pragma unroll
    for (int o = 1; o < 32; o <<= 1) {
        float n = __shfl_up_sync(m, v, o);
        if ((t & 31) >= o) v += n;
    }
    __shared__ float wsum[8];
    if ((t & 31) == 31) wsum[t >> 5] = v;
    __syncthreads();
    if (t < 8) {
        float w = wsum[t];
        #pragma unroll
        for (int o = 1; o < 8; o <<= 1) {
            float n = __shfl_up_sync(0xffu, w, o);
            if (t >= o) w += n;
        }
        wsum[t] = w;
    }
    __syncthreads();
    float excl = (v - s) + ((t >= 32) ? wsum[(t >> 5) - 1] : 0.f);

    float run = excl;
    float acc = 0.f;
    #pragma unroll
    for (int k = 0; k < CHUNK; k++) {
        int i = i0 + k;
        if (i < NUM_SAMPLES) {
            run += loc[k];                          // integral_i (TIMESTEP=1)
            float dens = loc[k] * exp2f(-L2E * run);
            float wgt = (i == NUM_SAMPLES - 1) ? 0.5f : 1.0f;  // i==0 term is 0
            acc = fmaf(wgt * (float)i, dens, acc);
        }
    }

    #pragma unroll
    for (int o = 16; o > 0; o >>= 1) acc += __shfl_down_sync(m, acc, o);
    __shared__ float rsum[8];
    if ((t & 31) == 0) rsum[t >> 5] = acc;
    __syncthreads();
    if (t == 0) {
        float tot = 0.f;
        #pragma unroll
        for (int wgrp = 0; wgrp < 8; wgrp++) tot += rsum[wgrp];
        out[(size_t)2 * BATCH * N_NODES + b] = tot;
    }
}

// ---------------------------------------------------------------------------
extern "C" void kernel_launch(void* const* d_in, const int* in_sizes, int n_in,
                              void* d_out, int out_size)
{
    (void)in_sizes; (void)n_in; (void)out_size;
    const float* emb   = (const float*)d_in[0];
    const int*   assoc = (const int*)  d_in[1];
    const int*   src   = (const int*)  d_in[2];
    const int*   pdst  = (const int*)  d_in[3];
    const float* lu    = (const float*)d_in[5];
    const float* ct    = (const float*)d_in[6];
    const int*   et    = (const int*)  d_in[7];
    const float* W0    = (const float*)d_in[8];
    const float* b0    = (const float*)d_in[9];
    const float* W1    = (const float*)d_in[10];
    const float* b1    = (const float*)d_in[11];
    const float* psi   = (const float*)d_in[12];
    const float* alpha = (const float*)d_in[13];
    const float* w_t   = (const float*)d_in[14];

    decoder_kernel<<<TOTAL_BLOCKS, 256>>>((float*)d_out, emb, assoc, src, pdst,
                                          lu, ct, et, W0, b0, W1, b1,
                                          psi, alpha, w_t);
}